// round 6
// baseline (speedup 1.0000x reference)
#include <cuda_runtime.h>
#include <cstdint>

// ---------------------------------------------------------------------------
// FocalLoss_84645215469642 — sm_100a
// Inputs (metadata order):
//   d_in[0] classifications [B, A, C]  float32
//   d_in[1] regressions     [B, A, 3]  float32
//   d_in[2] anchors         [1, A, 3]  float32
//   d_in[3] annotations     [B, M, 4]  float32   (x, y, alpha, class; class==-1 invalid)
// Output: 3 float32 scalars: cls_loss, xy_loss, ang_loss (batch means)
// ---------------------------------------------------------------------------

#define MAX_B 8
#define MAX_A (1 << 18)
#define MAX_M 64
#define MAX_SEG (MAX_A / 256)
#define NSLOT 32
#define UNROLL 8

// scratch (device globals — no allocations allowed)
__device__ uint16_t g_meta[MAX_B * MAX_A];        // amin(6b) | state(2b) | class(8b)
__device__ int      g_segcnt[MAX_B * MAX_SEG];    // positives per 256-anchor segment
__device__ int      g_table[MAX_B * MAX_M];       // table[k] = ann idx of k-th positive anchor
__device__ int      g_numpos[MAX_B];
__device__ double   g_cls_part[MAX_B * NSLOT];
__device__ double   g_xy_part [MAX_B * NSLOT];
__device__ double   g_ang_part[MAX_B * NSLOT];
__device__ unsigned g_done;                        // zero-init; reset by last block

// ---------------------------------------------------------------------------
// assign: one thread per anchor. argmin over annotations, 3-state target,
// packed meta; block-level positive count -> g_segcnt.
// ---------------------------------------------------------------------------
__global__ void assign_kernel(const float* __restrict__ anchors,
                              const float* __restrict__ ann,
                              int A, int M) {
    __shared__ float s_ann[MAX_M * 4];
    __shared__ int   s_wcnt[8];
    int b = blockIdx.y;
    for (int i = threadIdx.x; i < M * 4; i += blockDim.x)
        s_ann[i] = ann[b * M * 4 + i];
    __syncthreads();

    int a = blockIdx.x * blockDim.x + threadIdx.x;
    bool in = (a < A);
    int aa = in ? a : 0;

    float ax  = anchors[aa * 3 + 0];
    float ay  = anchors[aa * 3 + 1];
    float aal = anchors[aa * 3 + 2];

    float best = 3.4e38f;
    int bi = 0;
    #pragma unroll 4
    for (int m = 0; m < M; m++) {
        float cx = s_ann[m * 4 + 0];
        float cy = s_ann[m * 4 + 1];
        bool valid = (s_ann[m * 4 + 3] != -1.0f);
        float dx = ax - cx, dy = ay - cy;
        float d2 = valid ? fmaf(dx, dx, dy * dy) : 1e18f;   // BIG^2
        if (d2 < best) { best = d2; bi = m; }
    }
    float dal = fabsf(aal - s_ann[bi * 4 + 2]);

    // pos: dxy<=5 && dal<=0.3 ; neg: dxy>=7.5 || dal>=0.45 ; else ignore
    bool pos = (best <= 25.0f) && (dal <= 0.3f);
    int state;
    if (pos)                                 state = 2;
    else if (best >= 56.25f || dal >= 0.45f) state = 1;
    else                                     state = 0;

    int cls = (int)s_ann[bi * 4 + 3];
    if (cls < 0) cls = 0;

    if (in)
        g_meta[b * A + a] = (uint16_t)((bi & 63) | (state << 6) | ((cls & 0xFF) << 8));

    unsigned bal = __ballot_sync(0xffffffffu, pos && in);
    int lane = threadIdx.x & 31, wid = threadIdx.x >> 5;
    if (lane == 0) s_wcnt[wid] = __popc(bal);
    __syncthreads();
    if (threadIdx.x == 0) {
        int tot = 0;
        #pragma unroll
        for (int w = 0; w < 8; w++) tot += s_wcnt[w];
        g_segcnt[b * MAX_SEG + blockIdx.x] = tot;
    }
}

// ---------------------------------------------------------------------------
// scan: one block per image. Prefix-scan segment counts -> num_pos; walk only
// segments whose exclusive prefix < M to fill table. Also zeroes accumulators.
// ---------------------------------------------------------------------------
__global__ void scan_kernel(int A, int M, int NSEG) {
    int b = blockIdx.x;
    int t = threadIdx.x;
    __shared__ int s_dat[256];

    if (t < NSLOT) {
        g_cls_part[b * NSLOT + t] = 0.0;
        g_xy_part [b * NSLOT + t] = 0.0;
        g_ang_part[b * NSLOT + t] = 0.0;
    }
    for (int i = t; i < M; i += blockDim.x) g_table[b * M + i] = 0;
    __syncthreads();

    int base = 0;
    for (int s0 = 0; s0 < NSEG; s0 += blockDim.x) {
        int seg = s0 + t;
        int cnt = (seg < NSEG) ? g_segcnt[b * MAX_SEG + seg] : 0;
        s_dat[t] = cnt;
        __syncthreads();
        #pragma unroll
        for (int off = 1; off < 256; off <<= 1) {
            int v = (t >= off) ? s_dat[t - off] : 0;
            __syncthreads();
            s_dat[t] += v;
            __syncthreads();
        }
        int incl  = s_dat[t];
        int total = s_dat[255];
        int epref = base + incl - cnt;

        if (seg < NSEG && cnt > 0 && epref < M) {
            int r = epref;
            int abase = b * A + seg * 256;
            int lim = min(256, A - seg * 256);
            #pragma unroll 8
            for (int j = 0; j < lim; j++) {
                if (r >= M) break;
                uint32_t mm = g_meta[abase + j];
                if (((mm >> 6) & 3u) == 2u) { g_table[b * M + r] = (int)(mm & 63u); r++; }
            }
        }
        base += total;
        __syncthreads();
    }
    if (t == 0) g_numpos[b] = base;
}

__device__ __forceinline__ float focal_elem(float c, bool is_one, bool active) {
    c = fminf(fmaxf(c, 1e-4f), 0.9999f);
    float o = 1.0f - c;
    float w = is_one ? 0.25f * o * o : 0.75f * c * c;
    float l = -__logf(is_one ? c : o);
    return active ? w * l : 0.0f;
}

__device__ __forceinline__ float smooth_l1(float d) {
    return (d <= 1.0f / 9.0f) ? (4.5f * d * d) : (d - 0.5f / 9.0f);
}

// ---------------------------------------------------------------------------
// fused focal + regression + finalize (last-block-done).
// Flat float4-index space per image: N4 = A*C/4 float4s.
// Thread processes UNROLL=8 independent float4s per batch (front-batched LDGs).
// anchor = idx >> shift (C/4 pow2) or idx / f4pa ; col = (idx & (f4pa-1))*4.
// The (col==0 && positive) thread also handles the anchor's regression loss.
// ---------------------------------------------------------------------------
__global__ void fused_kernel(const float4* __restrict__ cls4,
                             const float* __restrict__ regs,
                             const float* __restrict__ anchors,
                             const float* __restrict__ ann,
                             float* __restrict__ out,
                             int A, int C, int M, int B,
                             int N4, int shift, int f4pa, int total_blocks) {
    int b  = blockIdx.y;
    int t  = threadIdx.x;
    const uint16_t* meta_b = g_meta + (size_t)b * A;
    const float4*   cls_b  = cls4 + (size_t)b * N4;

    float cl_acc = 0.0f, xy_acc = 0.0f, ang_acc = 0.0f;
    int stride = gridDim.x * blockDim.x;

    for (int base = blockIdx.x * blockDim.x + t; base < N4; base += stride * UNROLL) {
        int      idx[UNROLL];
        bool     ok [UNROLL];
        float4   v  [UNROLL];
        uint32_t mm [UNROLL];

        #pragma unroll
        for (int k = 0; k < UNROLL; k++) {
            idx[k] = base + k * stride;
            ok[k]  = (idx[k] < N4);
        }
        // front-batched 128-bit loads (independent addresses -> high MLP)
        #pragma unroll
        for (int k = 0; k < UNROLL; k++)
            if (ok[k]) v[k] = __ldg(&cls_b[idx[k]]);
        #pragma unroll
        for (int k = 0; k < UNROLL; k++)
            if (ok[k]) {
                int a = (shift >= 0) ? (idx[k] >> shift) : (idx[k] / f4pa);
                mm[k] = meta_b[a];
            }

        #pragma unroll
        for (int k = 0; k < UNROLL; k++) {
            if (!ok[k]) continue;
            int a   = (shift >= 0) ? (idx[k] >> shift) : (idx[k] / f4pa);
            int col = (idx[k] - a * f4pa) << 2;
            int state = (int)((mm[k] >> 6) & 3u);
            bool active = (state != 0);
            int tgt = (state == 2) ? (int)(mm[k] >> 8) : -1;

            cl_acc += focal_elem(v[k].x, col + 0 == tgt, active);
            cl_acc += focal_elem(v[k].y, col + 1 == tgt, active);
            cl_acc += focal_elem(v[k].z, col + 2 == tgt, active);
            cl_acc += focal_elem(v[k].w, col + 3 == tgt, active);

            if (col == 0 && state == 2) {
                int gi = g_table[b * M + (mm[k] & 63u)];
                const float* g  = ann + (size_t)(b * M + gi) * 4;
                const float* rg = regs + ((size_t)b * A + a) * 3;
                float tx = g[0] - anchors[a * 3 + 0];
                float ty = g[1] - anchors[a * 3 + 1];
                float ta = g[2] - anchors[a * 3 + 2];
                xy_acc  += smooth_l1(fabsf(tx - rg[0])) + smooth_l1(fabsf(ty - rg[1]));
                ang_acc += 1.0f - cosf(ta - rg[2]);
            }
        }
    }

    // block reduce 3 values
    __shared__ float s_c[8], s_x[8], s_a[8];
    #pragma unroll
    for (int o = 16; o > 0; o >>= 1) {
        cl_acc  += __shfl_down_sync(0xffffffffu, cl_acc,  o);
        xy_acc  += __shfl_down_sync(0xffffffffu, xy_acc,  o);
        ang_acc += __shfl_down_sync(0xffffffffu, ang_acc, o);
    }
    int lane = t & 31, wid = t >> 5;
    if (lane == 0) { s_c[wid] = cl_acc; s_x[wid] = xy_acc; s_a[wid] = ang_acc; }
    __syncthreads();
    if (wid == 0) {
        float vc = (lane < 8) ? s_c[lane] : 0.0f;
        float vx = (lane < 8) ? s_x[lane] : 0.0f;
        float va = (lane < 8) ? s_a[lane] : 0.0f;
        #pragma unroll
        for (int o = 4; o > 0; o >>= 1) {
            vc += __shfl_down_sync(0xffffffffu, vc, o);
            vx += __shfl_down_sync(0xffffffffu, vx, o);
            va += __shfl_down_sync(0xffffffffu, va, o);
        }
        if (lane == 0) {
            int slot = blockIdx.x & (NSLOT - 1);
            atomicAdd(&g_cls_part[b * NSLOT + slot], (double)vc);
            if (vx != 0.0f) atomicAdd(&g_xy_part [b * NSLOT + slot], (double)vx);
            if (va != 0.0f) atomicAdd(&g_ang_part[b * NSLOT + slot], (double)va);
        }
    }

    // last-block-done finalize
    __shared__ bool s_last;
    __threadfence();
    __syncthreads();
    if (t == 0) {
        unsigned old = atomicAdd(&g_done, 1u);
        s_last = (old == (unsigned)(total_blocks - 1));
    }
    __syncthreads();
    if (!s_last) return;
    __threadfence();

    __shared__ double f_cl[8], f_xy[8], f_ang[8];
    if (wid < B) {
        double sc = g_cls_part[wid * NSLOT + lane];
        double sx = g_xy_part [wid * NSLOT + lane];
        double sa = g_ang_part[wid * NSLOT + lane];
        #pragma unroll
        for (int o = 16; o > 0; o >>= 1) {
            sc += __shfl_down_sync(0xffffffffu, sc, o);
            sx += __shfl_down_sync(0xffffffffu, sx, o);
            sa += __shfl_down_sync(0xffffffffu, sa, o);
        }
        if (lane == 0) {
            double np = (double)max(g_numpos[wid], 1);
            f_cl[wid]  = sc / np;
            f_xy[wid]  = sx / (2.0 * np);
            f_ang[wid] = sa / np;
        }
    }
    __syncthreads();
    if (t == 0) {
        double cl = 0.0, xy = 0.0, ag = 0.0;
        for (int bb = 0; bb < B; bb++) { cl += f_cl[bb]; xy += f_xy[bb]; ag += f_ang[bb]; }
        out[0] = (float)(cl / B);
        out[1] = (float)(xy / B);
        out[2] = (float)(ag / B);
        g_done = 0;   // reset for deterministic graph replay
    }
}

extern "C" void kernel_launch(void* const* d_in, const int* in_sizes, int n_in,
                              void* d_out, int out_size) {
    const float* cls     = (const float*)d_in[0];
    const float* regs    = (const float*)d_in[1];
    const float* anchors = (const float*)d_in[2];
    const float* ann     = (const float*)d_in[3];
    float* out = (float*)d_out;

    int A = in_sizes[2] / 3;                 // anchors [1, A, 3]
    int B = in_sizes[1] / (3 * A);           // regressions [B, A, 3]
    int C = in_sizes[0] / (B * A);           // classifications [B, A, C]
    int M = in_sizes[3] / (4 * B);           // annotations [B, M, 4]
    int NSEG = (A + 255) / 256;

    dim3 ag(NSEG, B);
    assign_kernel<<<ag, 256>>>(anchors, ann, A, M);

    scan_kernel<<<B, 256>>>(A, M, NSEG);

    int f4pa = C / 4;                        // float4s per anchor (C assumed %4==0)
    int N4 = A * f4pa;
    int shift = -1;
    if ((f4pa & (f4pa - 1)) == 0) {          // pow2 -> shift path
        shift = 0;
        while ((1 << shift) != f4pa) shift++;
    }
    dim3 fg(512, B);
    fused_kernel<<<fg, 256>>>((const float4*)cls, regs, anchors, ann, out,
                              A, C, M, B, N4, shift, f4pa, 512 * B);
}

// round 9
// speedup vs baseline: 1.2236x; 1.2236x over previous
#include <cuda_runtime.h>
#include <cstdint>

// ---------------------------------------------------------------------------
// FocalLoss_84645215469642 — sm_100a
// Inputs (metadata order):
//   d_in[0] classifications [B, A, C]  float32
//   d_in[1] regressions     [B, A, 3]  float32
//   d_in[2] anchors         [1, A, 3]  float32
//   d_in[3] annotations     [B, M, 4]  float32   (x, y, alpha, class; class==-1 invalid)
// Output: 3 float32 scalars: cls_loss, xy_loss, ang_loss (batch means)
// ---------------------------------------------------------------------------

#define MAX_B 8
#define MAX_A (1 << 18)
#define MAX_M 64
#define MAX_SEG (MAX_A / 256)
#define NSLOT 32
#define NBLK 512

// scratch (device globals — no allocations allowed)
__device__ uint16_t g_meta[MAX_B * MAX_A];        // amin(6b) | state(2b) | class(8b)
__device__ int      g_segcnt[MAX_B * MAX_SEG];    // positives per 256-anchor segment
__device__ int      g_table[MAX_B * MAX_M];       // table[k] = ann idx of k-th positive anchor
__device__ int      g_numpos[MAX_B];
__device__ double   g_cls_part[MAX_B * NSLOT];
__device__ double   g_xy_part [MAX_B * NSLOT];
__device__ double   g_ang_part[MAX_B * NSLOT];
__device__ unsigned g_done;                        // zero-init; reset by last block

// ---------------------------------------------------------------------------
// assign: one thread per anchor. float4-staged annotations; invalid anns get
// x=1e9 so d2==1e18 (same BIG^2 as the masked reference) with no per-iter
// select. One broadcast LDS.128 per inner iteration.
// ---------------------------------------------------------------------------
__global__ void assign_kernel(const float* __restrict__ anchors,
                              const float* __restrict__ ann,
                              int A, int M) {
    __shared__ float4 s_ann[MAX_M];
    __shared__ int    s_wcnt[8];
    int b = blockIdx.y;
    for (int i = threadIdx.x; i < M; i += blockDim.x) {
        float4 f = ((const float4*)(ann + (size_t)b * M * 4))[i];
        if (f.w == -1.0f) f.x = 1e9f;           // invalid -> d2 = 1e18
        s_ann[i] = f;
    }
    __syncthreads();

    int a = blockIdx.x * blockDim.x + threadIdx.x;
    bool in = (a < A);
    int aa = in ? a : 0;

    float ax  = anchors[aa * 3 + 0];
    float ay  = anchors[aa * 3 + 1];
    float aal = anchors[aa * 3 + 2];

    float best = 3.4e38f;
    int bi = 0;
    #pragma unroll 4
    for (int m = 0; m < M; m++) {
        float4 f = s_ann[m];
        float dx = ax - f.x, dy = ay - f.y;
        float d2 = fmaf(dx, dx, dy * dy);
        if (d2 < best) { best = d2; bi = m; }
    }
    float4 bf = s_ann[bi];
    float dal = fabsf(aal - bf.z);

    // pos: dxy<=5 && dal<=0.3 ; neg: dxy>=7.5 || dal>=0.45 ; else ignore
    bool pos = (best <= 25.0f) && (dal <= 0.3f);
    int state;
    if (pos)                                 state = 2;
    else if (best >= 56.25f || dal >= 0.45f) state = 1;
    else                                     state = 0;

    int cls = (int)bf.w;
    if (cls < 0) cls = 0;

    if (in)
        g_meta[b * A + a] = (uint16_t)((bi & 63) | (state << 6) | ((cls & 0xFF) << 8));

    unsigned bal = __ballot_sync(0xffffffffu, pos && in);
    int lane = threadIdx.x & 31, wid = threadIdx.x >> 5;
    if (lane == 0) s_wcnt[wid] = __popc(bal);
    __syncthreads();
    if (threadIdx.x == 0) {
        int tot = 0;
        #pragma unroll
        for (int w = 0; w < 8; w++) tot += s_wcnt[w];
        g_segcnt[b * MAX_SEG + blockIdx.x] = tot;
    }
}

// ---------------------------------------------------------------------------
// scan: one block per image. Prefix-scan segment counts -> num_pos; walk only
// segments whose exclusive prefix < M to fill table. Also zeroes accumulators.
// ---------------------------------------------------------------------------
__global__ void scan_kernel(int A, int M, int NSEG) {
    int b = blockIdx.x;
    int t = threadIdx.x;
    __shared__ int s_dat[256];

    if (t < NSLOT) {
        g_cls_part[b * NSLOT + t] = 0.0;
        g_xy_part [b * NSLOT + t] = 0.0;
        g_ang_part[b * NSLOT + t] = 0.0;
    }
    for (int i = t; i < M; i += blockDim.x) g_table[b * M + i] = 0;
    __syncthreads();

    int base = 0;
    for (int s0 = 0; s0 < NSEG; s0 += blockDim.x) {
        int seg = s0 + t;
        int cnt = (seg < NSEG) ? g_segcnt[b * MAX_SEG + seg] : 0;
        s_dat[t] = cnt;
        __syncthreads();
        #pragma unroll
        for (int off = 1; off < 256; off <<= 1) {
            int v = (t >= off) ? s_dat[t - off] : 0;
            __syncthreads();
            s_dat[t] += v;
            __syncthreads();
        }
        int incl  = s_dat[t];
        int total = s_dat[255];
        int epref = base + incl - cnt;

        if (seg < NSEG && cnt > 0 && epref < M) {
            int r = epref;
            int abase = b * A + seg * 256;
            int lim = min(256, A - seg * 256);
            #pragma unroll 8
            for (int j = 0; j < lim; j++) {
                if (r >= M) break;
                uint32_t mm = g_meta[abase + j];
                if (((mm >> 6) & 3u) == 2u) { g_table[b * M + r] = (int)(mm & 63u); r++; }
            }
        }
        base += total;
        __syncthreads();
    }
    if (t == 0) g_numpos[b] = base;
}

__device__ __forceinline__ float focal_elem(float c, bool is_one, bool active) {
    c = fminf(fmaxf(c, 1e-4f), 0.9999f);
    float o = 1.0f - c;
    float w = is_one ? 0.25f * o * o : 0.75f * c * c;
    float l = -__logf(is_one ? c : o);
    return active ? w * l : 0.0f;
}

__device__ __forceinline__ float smooth_l1(float d) {
    return (d <= 1.0f / 9.0f) ? (4.5f * d * d) : (d - 0.5f / 9.0f);
}

// ---------------------------------------------------------------------------
// fused focal + regression + finalize (last-block-done).
// Layout: la = t>>4 (anchor in 16-group), c4 = t&15 (float4 col). A warp's
// load = 512B fully coalesced. Block owns a contiguous [aStart, aEnd) chunk;
// group loop hand-unrolled x4 with uniform bounds: 4 meta + 4 float4 loads
// front-batched per body (high MLP, no per-lane guards).
// CF4 > 0 => compile-time f4pa (col loop vanishes). CF4 == 0 => runtime.
// ---------------------------------------------------------------------------
template<int CF4>
__global__ void fused_kernel(const float4* __restrict__ cls4,
                             const float* __restrict__ regs,
                             const float* __restrict__ anchors,
                             const float* __restrict__ ann,
                             float* __restrict__ out,
                             int A, int M, int B,
                             int f4pa_rt, int chunk, int total_blocks) {
    const int f4pa = (CF4 > 0) ? CF4 : f4pa_rt;
    int b  = blockIdx.y;
    int t  = threadIdx.x;
    int la = t >> 4;       // 0..15 : anchor within group
    int c4 = t & 15;       // 0..15 : float4 column

    const uint16_t* meta_b = g_meta + (size_t)b * A;
    const float4*   cls_b  = cls4 + (size_t)b * A * f4pa;

    float cl_acc = 0.0f, xy_acc = 0.0f, ang_acc = 0.0f;

    int aStart = blockIdx.x * chunk;
    int aEnd   = min(aStart + chunk, A);

    int gb = aStart;
    // main path: 4 groups of 16 anchors per iteration, uniform bounds
    for (; gb + 64 <= aEnd; gb += 64) {
        int      a[4];
        uint32_t mm[4];
        float4   v[4];
        #pragma unroll
        for (int k = 0; k < 4; k++) a[k] = gb + k * 16 + la;
        #pragma unroll
        for (int k = 0; k < 4; k++) mm[k] = meta_b[a[k]];
        #pragma unroll
        for (int k = 0; k < 4; k++) v[k] = cls_b[(size_t)a[k] * f4pa + c4];

        #pragma unroll
        for (int k = 0; k < 4; k++) {
            int state = (int)((mm[k] >> 6) & 3u);
            bool active = (state != 0);
            int tgt = (state == 2) ? (int)(mm[k] >> 8) : -1;
            int col = c4 << 2;
            cl_acc += focal_elem(v[k].x, col + 0 == tgt, active);
            cl_acc += focal_elem(v[k].y, col + 1 == tgt, active);
            cl_acc += focal_elem(v[k].z, col + 2 == tgt, active);
            cl_acc += focal_elem(v[k].w, col + 3 == tgt, active);

            if (CF4 == 0) {   // generic wide-C fallback
                for (int cc = c4 + 16; cc < f4pa; cc += 16) {
                    float4 w = cls_b[(size_t)a[k] * f4pa + cc];
                    int cl2 = cc << 2;
                    cl_acc += focal_elem(w.x, cl2 + 0 == tgt, active);
                    cl_acc += focal_elem(w.y, cl2 + 1 == tgt, active);
                    cl_acc += focal_elem(w.z, cl2 + 2 == tgt, active);
                    cl_acc += focal_elem(w.w, cl2 + 3 == tgt, active);
                }
            }

            if (c4 == 0 && state == 2) {
                int gi = g_table[b * M + (mm[k] & 63u)];
                const float* g  = ann + (size_t)(b * M + gi) * 4;
                const float* rg = regs + ((size_t)b * A + a[k]) * 3;
                float tx = g[0] - anchors[a[k] * 3 + 0];
                float ty = g[1] - anchors[a[k] * 3 + 1];
                float ta = g[2] - anchors[a[k] * 3 + 2];
                xy_acc  += smooth_l1(fabsf(tx - rg[0])) + smooth_l1(fabsf(ty - rg[1]));
                ang_acc += 1.0f - cosf(ta - rg[2]);
            }
        }
    }
    // remainder: one 16-anchor group at a time
    for (; gb < aEnd; gb += 16) {
        int a = gb + la;
        if (a < aEnd) {
            uint32_t m = meta_b[a];
            int state = (int)((m >> 6) & 3u);
            bool active = (state != 0);
            int tgt = (state == 2) ? (int)(m >> 8) : -1;
            for (int cc = c4; cc < f4pa; cc += 16) {
                float4 v = cls_b[(size_t)a * f4pa + cc];
                int col = cc << 2;
                cl_acc += focal_elem(v.x, col + 0 == tgt, active);
                cl_acc += focal_elem(v.y, col + 1 == tgt, active);
                cl_acc += focal_elem(v.z, col + 2 == tgt, active);
                cl_acc += focal_elem(v.w, col + 3 == tgt, active);
            }
            if (c4 == 0 && state == 2) {
                int gi = g_table[b * M + (m & 63u)];
                const float* g  = ann + (size_t)(b * M + gi) * 4;
                const float* rg = regs + ((size_t)b * A + a) * 3;
                float tx = g[0] - anchors[a * 3 + 0];
                float ty = g[1] - anchors[a * 3 + 1];
                float ta = g[2] - anchors[a * 3 + 2];
                xy_acc  += smooth_l1(fabsf(tx - rg[0])) + smooth_l1(fabsf(ty - rg[1]));
                ang_acc += 1.0f - cosf(ta - rg[2]);
            }
        }
    }

    // block reduce 3 values
    __shared__ float s_c[8], s_x[8], s_a[8];
    #pragma unroll
    for (int o = 16; o > 0; o >>= 1) {
        cl_acc  += __shfl_down_sync(0xffffffffu, cl_acc,  o);
        xy_acc  += __shfl_down_sync(0xffffffffu, xy_acc,  o);
        ang_acc += __shfl_down_sync(0xffffffffu, ang_acc, o);
    }
    int lane = t & 31, wid = t >> 5;
    if (lane == 0) { s_c[wid] = cl_acc; s_x[wid] = xy_acc; s_a[wid] = ang_acc; }
    __syncthreads();
    if (wid == 0) {
        float vc = (lane < 8) ? s_c[lane] : 0.0f;
        float vx = (lane < 8) ? s_x[lane] : 0.0f;
        float va = (lane < 8) ? s_a[lane] : 0.0f;
        #pragma unroll
        for (int o = 4; o > 0; o >>= 1) {
            vc += __shfl_down_sync(0xffffffffu, vc, o);
            vx += __shfl_down_sync(0xffffffffu, vx, o);
            va += __shfl_down_sync(0xffffffffu, va, o);
        }
        if (lane == 0) {
            int slot = blockIdx.x & (NSLOT - 1);
            atomicAdd(&g_cls_part[b * NSLOT + slot], (double)vc);
            if (vx != 0.0f) atomicAdd(&g_xy_part [b * NSLOT + slot], (double)vx);
            if (va != 0.0f) atomicAdd(&g_ang_part[b * NSLOT + slot], (double)va);
        }
    }

    // last-block-done finalize
    __shared__ bool s_last;
    __threadfence();
    __syncthreads();
    if (t == 0) {
        unsigned old = atomicAdd(&g_done, 1u);
        s_last = (old == (unsigned)(total_blocks - 1));
    }
    __syncthreads();
    if (!s_last) return;
    __threadfence();

    __shared__ double f_cl[8], f_xy[8], f_ang[8];
    if (wid < B) {
        double sc = g_cls_part[wid * NSLOT + lane];
        double sx = g_xy_part [wid * NSLOT + lane];
        double sa = g_ang_part[wid * NSLOT + lane];
        #pragma unroll
        for (int o = 16; o > 0; o >>= 1) {
            sc += __shfl_down_sync(0xffffffffu, sc, o);
            sx += __shfl_down_sync(0xffffffffu, sx, o);
            sa += __shfl_down_sync(0xffffffffu, sa, o);
        }
        if (lane == 0) {
            double np = (double)max(g_numpos[wid], 1);
            f_cl[wid]  = sc / np;
            f_xy[wid]  = sx / (2.0 * np);
            f_ang[wid] = sa / np;
        }
    }
    __syncthreads();
    if (t == 0) {
        double cl = 0.0, xy = 0.0, ag = 0.0;
        for (int bb = 0; bb < B; bb++) { cl += f_cl[bb]; xy += f_xy[bb]; ag += f_ang[bb]; }
        out[0] = (float)(cl / B);
        out[1] = (float)(xy / B);
        out[2] = (float)(ag / B);
        g_done = 0;   // reset for deterministic graph replay
    }
}

extern "C" void kernel_launch(void* const* d_in, const int* in_sizes, int n_in,
                              void* d_out, int out_size) {
    const float* cls     = (const float*)d_in[0];
    const float* regs    = (const float*)d_in[1];
    const float* anchors = (const float*)d_in[2];
    const float* ann     = (const float*)d_in[3];
    float* out = (float*)d_out;

    int A = in_sizes[2] / 3;                 // anchors [1, A, 3]
    int B = in_sizes[1] / (3 * A);           // regressions [B, A, 3]
    int C = in_sizes[0] / (B * A);           // classifications [B, A, C]
    int M = in_sizes[3] / (4 * B);           // annotations [B, M, 4]
    int NSEG = (A + 255) / 256;

    dim3 ag(NSEG, B);
    assign_kernel<<<ag, 256>>>(anchors, ann, A, M);

    scan_kernel<<<B, 256>>>(A, M, NSEG);

    int f4pa = C / 4;                        // float4s per anchor (C % 4 == 0)
    int chunk = ((A + NBLK - 1) / NBLK + 15) & ~15;  // multiple of 16
    dim3 fg(NBLK, B);
    if (f4pa == 16)
        fused_kernel<16><<<fg, 256>>>((const float4*)cls, regs, anchors, ann, out,
                                      A, M, B, f4pa, chunk, NBLK * B);
    else
        fused_kernel<0><<<fg, 256>>>((const float4*)cls, regs, anchors, ann, out,
                                     A, M, B, f4pa, chunk, NBLK * B);
}

// round 10
// speedup vs baseline: 1.9757x; 1.6146x over previous
#include <cuda_runtime.h>
#include <cstdint>

// ---------------------------------------------------------------------------
// FocalLoss_84645215469642 — sm_100a
// Inputs (metadata order):
//   d_in[0] classifications [B, A, C]  float32
//   d_in[1] regressions     [B, A, 3]  float32
//   d_in[2] anchors         [1, A, 3]  float32
//   d_in[3] annotations     [B, M, 4]  float32   (x, y, alpha, class; class==-1 invalid)
// Output: 3 float32 scalars: cls_loss, xy_loss, ang_loss (batch means)
// ---------------------------------------------------------------------------

#define MAX_B 8
#define MAX_A (1 << 18)
#define MAX_M 64
#define NSLOT 32
#define NBLK 512
#define POSCAP 4096   // per-image positive-list capacity (geometric bound ~1.4K)

// scratch (device globals — no allocations allowed)
__device__ uint16_t g_meta[MAX_B * MAX_A];          // amin(6b) | state(2b) | class(8b)
__device__ uint32_t g_poslist[MAX_B * POSCAP];      // (anchor<<6) | amin, unordered
__device__ int      g_poscnt[MAX_B];                // atomic counter (reset by fixup)
__device__ int      g_table[MAX_B * MAX_M];         // table[k] = ann idx of k-th positive anchor
__device__ int      g_numpos[MAX_B];
__device__ double   g_cls_part[MAX_B * NSLOT];
__device__ double   g_xy_part [MAX_B * NSLOT];
__device__ double   g_ang_part[MAX_B * NSLOT];
__device__ unsigned g_done;                          // zero-init; reset by last block

// ---------------------------------------------------------------------------
// assign: 2 anchors per thread (shared LDS.128 annotation reads). Invalid
// annotations get x=1e9 so d2==1e18 (same BIG^2 as the reference mask).
// Positive anchors push (a<<6 | amin) into the per-image list.
// ---------------------------------------------------------------------------
__global__ void assign_kernel(const float* __restrict__ anchors,
                              const float* __restrict__ ann,
                              int A, int M) {
    __shared__ float4 s_ann[MAX_M];
    int b = blockIdx.y;
    for (int i = threadIdx.x; i < M; i += blockDim.x) {
        float4 f = ((const float4*)(ann + (size_t)b * M * 4))[i];
        if (f.w == -1.0f) f.x = 1e9f;           // invalid -> d2 = 1e18
        s_ann[i] = f;
    }
    __syncthreads();

    int a0 = blockIdx.x * 512 + threadIdx.x;
    int a1 = a0 + 256;
    bool in0 = (a0 < A), in1 = (a1 < A);
    int aa0 = in0 ? a0 : 0, aa1 = in1 ? a1 : 0;

    float ax0 = anchors[aa0 * 3 + 0], ay0 = anchors[aa0 * 3 + 1], al0 = anchors[aa0 * 3 + 2];
    float ax1 = anchors[aa1 * 3 + 0], ay1 = anchors[aa1 * 3 + 1], al1 = anchors[aa1 * 3 + 2];

    float b0 = 3.4e38f, b1 = 3.4e38f;
    int i0 = 0, i1 = 0;
    #pragma unroll 4
    for (int m = 0; m < M; m++) {
        float4 f = s_ann[m];
        float dx0 = ax0 - f.x, dy0 = ay0 - f.y;
        float dx1 = ax1 - f.x, dy1 = ay1 - f.y;
        float d20 = fmaf(dx0, dx0, dy0 * dy0);
        float d21 = fmaf(dx1, dx1, dy1 * dy1);
        if (d20 < b0) { b0 = d20; i0 = m; }
        if (d21 < b1) { b1 = d21; i1 = m; }
    }

    #pragma unroll
    for (int k = 0; k < 2; k++) {
        bool  in   = k ? in1 : in0;
        int   a    = k ? a1  : a0;
        float best = k ? b1  : b0;
        int   bi   = k ? i1  : i0;
        float aal  = k ? al1 : al0;
        if (!in) continue;

        float4 bf = s_ann[bi];
        float dal = fabsf(aal - bf.z);

        // pos: dxy<=5 && dal<=0.3 ; neg: dxy>=7.5 || dal>=0.45 ; else ignore
        bool pos = (best <= 25.0f) && (dal <= 0.3f);
        int state;
        if (pos)                                 state = 2;
        else if (best >= 56.25f || dal >= 0.45f) state = 1;
        else                                     state = 0;

        int cls = (int)bf.w;
        if (cls < 0) cls = 0;

        g_meta[b * A + a] = (uint16_t)((bi & 63) | (state << 6) | ((cls & 0xFF) << 8));

        if (pos) {
            int idx = atomicAdd(&g_poscnt[b], 1);
            if (idx < POSCAP)
                g_poslist[b * POSCAP + idx] = ((uint32_t)a << 6) | (uint32_t)(bi & 63);
        }
    }
}

// ---------------------------------------------------------------------------
// fixup: one block per image. Rank the unordered positive list by anchor
// index (value order == anchor order since a occupies high bits) and fill
// table[rank] = amin for rank < M. Also zeroes accumulators/table and resets
// the atomic counter for deterministic graph replay.
// ---------------------------------------------------------------------------
__global__ void fixup_kernel(int M) {
    int b = blockIdx.x;
    int t = threadIdx.x;
    __shared__ uint32_t s_list[POSCAP];
    __shared__ int s_n;

    if (t == 0) s_n = min(g_poscnt[b], POSCAP);
    if (t < NSLOT) {
        g_cls_part[b * NSLOT + t] = 0.0;
        g_xy_part [b * NSLOT + t] = 0.0;
        g_ang_part[b * NSLOT + t] = 0.0;
    }
    for (int i = t; i < M; i += blockDim.x) g_table[b * M + i] = 0;
    __syncthreads();

    int n = s_n;
    for (int i = t; i < n; i += blockDim.x) s_list[i] = g_poslist[b * POSCAP + i];
    __syncthreads();

    for (int i = t; i < n; i += blockDim.x) {
        uint32_t v = s_list[i];
        int rank = 0;
        for (int j = 0; j < n; j++) rank += (s_list[j] < v);
        if (rank < M) g_table[b * M + rank] = (int)(v & 63u);
    }

    if (t == 0) {
        g_numpos[b] = g_poscnt[b];
        g_poscnt[b] = 0;   // reset for next graph replay
    }
}

__device__ __forceinline__ float focal_elem(float c, bool is_one, bool active) {
    c = fminf(fmaxf(c, 1e-4f), 0.9999f);
    float o = 1.0f - c;
    float w = is_one ? 0.25f * o * o : 0.75f * c * c;
    float l = -__logf(is_one ? c : o);
    return active ? w * l : 0.0f;
}

__device__ __forceinline__ float smooth_l1(float d) {
    return (d <= 1.0f / 9.0f) ? (4.5f * d * d) : (d - 0.5f / 9.0f);
}

// ---------------------------------------------------------------------------
// fused focal + regression + finalize (last-block-done).
// Layout: la = t>>4 (anchor in 16-group), c4 = t&15 (float4 col). A warp's
// load = 512B fully coalesced. Block owns a contiguous [aStart, aEnd) chunk;
// group loop hand-unrolled x4 with uniform bounds: 4 meta + 4 float4 loads
// front-batched per body (high MLP, no per-lane guards).
// CF4 > 0 => compile-time f4pa (col loop vanishes). CF4 == 0 => runtime.
// ---------------------------------------------------------------------------
template<int CF4>
__global__ void fused_kernel(const float4* __restrict__ cls4,
                             const float* __restrict__ regs,
                             const float* __restrict__ anchors,
                             const float* __restrict__ ann,
                             float* __restrict__ out,
                             int A, int M, int B,
                             int f4pa_rt, int chunk, int total_blocks) {
    const int f4pa = (CF4 > 0) ? CF4 : f4pa_rt;
    int b  = blockIdx.y;
    int t  = threadIdx.x;
    int la = t >> 4;       // 0..15 : anchor within group
    int c4 = t & 15;       // 0..15 : float4 column

    const uint16_t* meta_b = g_meta + (size_t)b * A;
    const float4*   cls_b  = cls4 + (size_t)b * A * f4pa;

    float cl_acc = 0.0f, xy_acc = 0.0f, ang_acc = 0.0f;

    int aStart = blockIdx.x * chunk;
    int aEnd   = min(aStart + chunk, A);

    int gb = aStart;
    // main path: 4 groups of 16 anchors per iteration, uniform bounds
    for (; gb + 64 <= aEnd; gb += 64) {
        int      a[4];
        uint32_t mm[4];
        float4   v[4];
        #pragma unroll
        for (int k = 0; k < 4; k++) a[k] = gb + k * 16 + la;
        #pragma unroll
        for (int k = 0; k < 4; k++) mm[k] = meta_b[a[k]];
        #pragma unroll
        for (int k = 0; k < 4; k++) v[k] = cls_b[(size_t)a[k] * f4pa + c4];

        #pragma unroll
        for (int k = 0; k < 4; k++) {
            int state = (int)((mm[k] >> 6) & 3u);
            bool active = (state != 0);
            int tgt = (state == 2) ? (int)(mm[k] >> 8) : -1;
            int col = c4 << 2;
            cl_acc += focal_elem(v[k].x, col + 0 == tgt, active);
            cl_acc += focal_elem(v[k].y, col + 1 == tgt, active);
            cl_acc += focal_elem(v[k].z, col + 2 == tgt, active);
            cl_acc += focal_elem(v[k].w, col + 3 == tgt, active);

            if (CF4 == 0) {   // generic wide-C fallback
                for (int cc = c4 + 16; cc < f4pa; cc += 16) {
                    float4 w = cls_b[(size_t)a[k] * f4pa + cc];
                    int cl2 = cc << 2;
                    cl_acc += focal_elem(w.x, cl2 + 0 == tgt, active);
                    cl_acc += focal_elem(w.y, cl2 + 1 == tgt, active);
                    cl_acc += focal_elem(w.z, cl2 + 2 == tgt, active);
                    cl_acc += focal_elem(w.w, cl2 + 3 == tgt, active);
                }
            }

            if (c4 == 0 && state == 2) {
                int gi = g_table[b * M + (mm[k] & 63u)];
                const float* g  = ann + (size_t)(b * M + gi) * 4;
                const float* rg = regs + ((size_t)b * A + a[k]) * 3;
                float tx = g[0] - anchors[a[k] * 3 + 0];
                float ty = g[1] - anchors[a[k] * 3 + 1];
                float ta = g[2] - anchors[a[k] * 3 + 2];
                xy_acc  += smooth_l1(fabsf(tx - rg[0])) + smooth_l1(fabsf(ty - rg[1]));
                ang_acc += 1.0f - cosf(ta - rg[2]);
            }
        }
    }
    // remainder: one 16-anchor group at a time
    for (; gb < aEnd; gb += 16) {
        int a = gb + la;
        if (a < aEnd) {
            uint32_t m = meta_b[a];
            int state = (int)((m >> 6) & 3u);
            bool active = (state != 0);
            int tgt = (state == 2) ? (int)(m >> 8) : -1;
            for (int cc = c4; cc < f4pa; cc += 16) {
                float4 v = cls_b[(size_t)a * f4pa + cc];
                int col = cc << 2;
                cl_acc += focal_elem(v.x, col + 0 == tgt, active);
                cl_acc += focal_elem(v.y, col + 1 == tgt, active);
                cl_acc += focal_elem(v.z, col + 2 == tgt, active);
                cl_acc += focal_elem(v.w, col + 3 == tgt, active);
            }
            if (c4 == 0 && state == 2) {
                int gi = g_table[b * M + (m & 63u)];
                const float* g  = ann + (size_t)(b * M + gi) * 4;
                const float* rg = regs + ((size_t)b * A + a) * 3;
                float tx = g[0] - anchors[a * 3 + 0];
                float ty = g[1] - anchors[a * 3 + 1];
                float ta = g[2] - anchors[a * 3 + 2];
                xy_acc  += smooth_l1(fabsf(tx - rg[0])) + smooth_l1(fabsf(ty - rg[1]));
                ang_acc += 1.0f - cosf(ta - rg[2]);
            }
        }
    }

    // block reduce 3 values
    __shared__ float s_c[8], s_x[8], s_a[8];
    #pragma unroll
    for (int o = 16; o > 0; o >>= 1) {
        cl_acc  += __shfl_down_sync(0xffffffffu, cl_acc,  o);
        xy_acc  += __shfl_down_sync(0xffffffffu, xy_acc,  o);
        ang_acc += __shfl_down_sync(0xffffffffu, ang_acc, o);
    }
    int lane = t & 31, wid = t >> 5;
    if (lane == 0) { s_c[wid] = cl_acc; s_x[wid] = xy_acc; s_a[wid] = ang_acc; }
    __syncthreads();
    if (wid == 0) {
        float vc = (lane < 8) ? s_c[lane] : 0.0f;
        float vx = (lane < 8) ? s_x[lane] : 0.0f;
        float va = (lane < 8) ? s_a[lane] : 0.0f;
        #pragma unroll
        for (int o = 4; o > 0; o >>= 1) {
            vc += __shfl_down_sync(0xffffffffu, vc, o);
            vx += __shfl_down_sync(0xffffffffu, vx, o);
            va += __shfl_down_sync(0xffffffffu, va, o);
        }
        if (lane == 0) {
            int slot = blockIdx.x & (NSLOT - 1);
            atomicAdd(&g_cls_part[b * NSLOT + slot], (double)vc);
            if (vx != 0.0f) atomicAdd(&g_xy_part [b * NSLOT + slot], (double)vx);
            if (va != 0.0f) atomicAdd(&g_ang_part[b * NSLOT + slot], (double)va);
        }
    }

    // last-block-done finalize
    __shared__ bool s_last;
    __threadfence();
    __syncthreads();
    if (t == 0) {
        unsigned old = atomicAdd(&g_done, 1u);
        s_last = (old == (unsigned)(total_blocks - 1));
    }
    __syncthreads();
    if (!s_last) return;
    __threadfence();

    __shared__ double f_cl[8], f_xy[8], f_ang[8];
    if (wid < B) {
        double sc = g_cls_part[wid * NSLOT + lane];
        double sx = g_xy_part [wid * NSLOT + lane];
        double sa = g_ang_part[wid * NSLOT + lane];
        #pragma unroll
        for (int o = 16; o > 0; o >>= 1) {
            sc += __shfl_down_sync(0xffffffffu, sc, o);
            sx += __shfl_down_sync(0xffffffffu, sx, o);
            sa += __shfl_down_sync(0xffffffffu, sa, o);
        }
        if (lane == 0) {
            double np = (double)max(g_numpos[wid], 1);
            f_cl[wid]  = sc / np;
            f_xy[wid]  = sx / (2.0 * np);
            f_ang[wid] = sa / np;
        }
    }
    __syncthreads();
    if (t == 0) {
        double cl = 0.0, xy = 0.0, ag = 0.0;
        for (int bb = 0; bb < B; bb++) { cl += f_cl[bb]; xy += f_xy[bb]; ag += f_ang[bb]; }
        out[0] = (float)(cl / B);
        out[1] = (float)(xy / B);
        out[2] = (float)(ag / B);
        g_done = 0;   // reset for deterministic graph replay
    }
}

extern "C" void kernel_launch(void* const* d_in, const int* in_sizes, int n_in,
                              void* d_out, int out_size) {
    const float* cls     = (const float*)d_in[0];
    const float* regs    = (const float*)d_in[1];
    const float* anchors = (const float*)d_in[2];
    const float* ann     = (const float*)d_in[3];
    float* out = (float*)d_out;

    int A = in_sizes[2] / 3;                 // anchors [1, A, 3]
    int B = in_sizes[1] / (3 * A);           // regressions [B, A, 3]
    int C = in_sizes[0] / (B * A);           // classifications [B, A, C]
    int M = in_sizes[3] / (4 * B);           // annotations [B, M, 4]

    dim3 ag((A + 511) / 512, B);
    assign_kernel<<<ag, 256>>>(anchors, ann, A, M);

    fixup_kernel<<<B, 256>>>(M);

    int f4pa = C / 4;                        // float4s per anchor (C % 4 == 0)
    int chunk = ((A + NBLK - 1) / NBLK + 15) & ~15;  // multiple of 16
    dim3 fg(NBLK, B);
    if (f4pa == 16)
        fused_kernel<16><<<fg, 256>>>((const float4*)cls, regs, anchors, ann, out,
                                      A, M, B, f4pa, chunk, NBLK * B);
    else
        fused_kernel<0><<<fg, 256>>>((const float4*)cls, regs, anchors, ann, out,
                                     A, M, B, f4pa, chunk, NBLK * B);
}